// round 2
// baseline (speedup 1.0000x reference)
#include <cuda_runtime.h>
#include <cuda_bf16.h>
#include <math.h>

// Problem constants (fixed by setup_inputs)
#define NN 100000          // nodes
#define NE 3200000         // edges
#define NG 256             // graphs

// -------- scratch (static device globals; no allocation) --------
// 16B alignment is REQUIRED for the float4 loads and v4 reds below.
__device__ __align__(16) float g_deg [NN];        // deg -> dinv (in place)
__device__ __align__(16) float g_u1  [NN * 32];   // (x@W1)*dinv
__device__ __align__(16) float g_acc1[NN * 32];   // scatter accumulator conv1
__device__ __align__(16) float g_u2  [NN * 24];   // (h1@W2)*dinv
__device__ __align__(16) float g_acc2[NN * 24];   // scatter accumulator conv2
__device__ __align__(16) float g_h2  [NN * 24];   // conv2 output (relu)
__device__ __align__(16) float g_nlog[NN];        // node logits, then exp(e) values
__device__ __align__(16) float g_gsum_h2[NG * 24];// per-graph sum of h2
__device__ __align__(16) float g_bfeat  [NG * 24];// per-graph sum n*h2
__device__ float    g_cnt  [NG];
__device__ unsigned g_gmax [NG];                  // ordered-uint encoded max of nlog
__device__ float    g_gsumn[NG];                  // per-graph sum exp

// ---------------- helpers ----------------
__device__ __forceinline__ void red_add_v4(float* addr, float a, float b, float c, float d) {
    asm volatile("red.global.add.v4.f32 [%0], {%1,%2,%3,%4};"
                 :: "l"(addr), "f"(a), "f"(b), "f"(c), "f"(d) : "memory");
}
__device__ __forceinline__ unsigned f2ord(float f) {
    unsigned u = __float_as_uint(f);
    return (u & 0x80000000u) ? ~u : (u | 0x80000000u);
}
__device__ __forceinline__ float ord2f(unsigned u) {
    return (u & 0x80000000u) ? __uint_as_float(u ^ 0x80000000u) : __uint_as_float(~u);
}

// ---------------- kernels ----------------

// zero / init all scratch (runs every launch; graph-replay safe)
__global__ void k_init() {
    int i = blockIdx.x * blockDim.x + threadIdx.x;     // grid covers NN*32
    if (i < NN * 32) g_acc1[i] = 0.0f;
    if (i < NN * 24) g_acc2[i] = 0.0f;
    if (i < NN)      g_deg[i]  = 1.0f;                 // self loop
    if (i < NG * 24) { g_gsum_h2[i] = 0.0f; g_bfeat[i] = 0.0f; }
    if (i < NG)      { g_cnt[i] = 0.0f; g_gmax[i] = 0u; g_gsumn[i] = 0.0f; }
}

// degree over targets (edge_index is int32 — JAX x64 is disabled!)
__global__ void k_deg(const int* __restrict__ cols, int E) {
    int e = blockIdx.x * blockDim.x + threadIdx.x;
    if (e < E) {
        unsigned c = (unsigned)cols[e];
        if (c < NN) atomicAdd(&g_deg[c], 1.0f);
    }
}

__global__ void k_dinv(int n) {
    int i = blockIdx.x * blockDim.x + threadIdx.x;
    if (i < n) g_deg[i] = rsqrtf(g_deg[i]);
}

// u1 = (x @ W1) * dinv   [NN,32]
__global__ __launch_bounds__(128) void k_gemm1(const float* __restrict__ x,
                                               const float* __restrict__ W1, int n) {
    __shared__ float Ws[32 * 32];
    for (int t = threadIdx.x; t < 1024; t += blockDim.x) Ws[t] = W1[t];
    __syncthreads();
    int i = blockIdx.x * blockDim.x + threadIdx.x;
    if (i >= n) return;
    float a[32];
#pragma unroll
    for (int j = 0; j < 32; j++) a[j] = 0.0f;
    const float4* xr = (const float4*)(x + (size_t)i * 32);
#pragma unroll
    for (int k4 = 0; k4 < 8; k4++) {
        float4 xv = xr[k4];
        float xs[4] = {xv.x, xv.y, xv.z, xv.w};
#pragma unroll
        for (int c = 0; c < 4; c++) {
            float v = xs[c];
            const float* wr = &Ws[(k4 * 4 + c) * 32];
#pragma unroll
            for (int j = 0; j < 32; j++) a[j] = fmaf(v, wr[j], a[j]);
        }
    }
    float di = g_deg[i];
    float4* out = (float4*)(g_u1 + (size_t)i * 32);
#pragma unroll
    for (int j4 = 0; j4 < 8; j4++)
        out[j4] = make_float4(a[j4*4]*di, a[j4*4+1]*di, a[j4*4+2]*di, a[j4*4+3]*di);
}

// scatter conv1: acc1[col] += u1[row]  (8 threads per edge, v4 reds)
__global__ __launch_bounds__(256) void k_scatter1(const int* __restrict__ rows,
                                                  const int* __restrict__ cols, int E) {
    __shared__ int sr[128], sc[128];
    int base = blockIdx.x * 128;
    int t = threadIdx.x;
    if (t < 128) { int e = base + t;        sr[t]        = (e < E) ? rows[e] : -1; }
    else         { int e = base + (t - 128); sc[t - 128] = (e < E) ? cols[e] : -1; }
    __syncthreads();
    int sub = t & 7;        // which float4 of the 32-float row
    int el  = t >> 3;       // 0..31
#pragma unroll
    for (int k = 0; k < 4; k++) {
        int le = el + k * 32;
        int r = sr[le];
        int c = sc[le];
        if ((unsigned)r < NN && (unsigned)c < NN) {
            const float4 v = *(const float4*)(g_u1 + (size_t)r * 32 + sub * 4);
            red_add_v4(g_acc1 + (size_t)c * 32 + sub * 4, v.x, v.y, v.z, v.w);
        }
    }
}

// h1 = relu(dinv*(acc1+u1)+b1); u2 = (h1@W2)*dinv   [NN,24]
__global__ __launch_bounds__(128) void k_fin1gemm2(const float* __restrict__ b1,
                                                   const float* __restrict__ W2, int n) {
    __shared__ float Ws[32 * 24];
    __shared__ float bs[32];
    for (int t = threadIdx.x; t < 32 * 24; t += blockDim.x) Ws[t] = W2[t];
    for (int t = threadIdx.x; t < 32; t += blockDim.x) bs[t] = b1[t];
    __syncthreads();
    int i = blockIdx.x * blockDim.x + threadIdx.x;
    if (i >= n) return;
    float di = g_deg[i];
    float h[32];
    const float4* ar = (const float4*)(g_acc1 + (size_t)i * 32);
    const float4* ur = (const float4*)(g_u1  + (size_t)i * 32);
#pragma unroll
    for (int j4 = 0; j4 < 8; j4++) {
        float4 a = ar[j4], u = ur[j4];
        h[j4*4+0] = fmaxf(di * (a.x + u.x) + bs[j4*4+0], 0.0f);
        h[j4*4+1] = fmaxf(di * (a.y + u.y) + bs[j4*4+1], 0.0f);
        h[j4*4+2] = fmaxf(di * (a.z + u.z) + bs[j4*4+2], 0.0f);
        h[j4*4+3] = fmaxf(di * (a.w + u.w) + bs[j4*4+3], 0.0f);
    }
    float a[24];
#pragma unroll
    for (int j = 0; j < 24; j++) a[j] = 0.0f;
#pragma unroll
    for (int k = 0; k < 32; k++) {
        float v = h[k];
        const float* wr = &Ws[k * 24];
#pragma unroll
        for (int j = 0; j < 24; j++) a[j] = fmaf(v, wr[j], a[j]);
    }
    float4* out = (float4*)(g_u2 + (size_t)i * 24);
#pragma unroll
    for (int j4 = 0; j4 < 6; j4++)
        out[j4] = make_float4(a[j4*4]*di, a[j4*4+1]*di, a[j4*4+2]*di, a[j4*4+3]*di);
}

// scatter conv2: acc2[col] += u2[row]  (6 threads per edge)
__global__ __launch_bounds__(192) void k_scatter2(const int* __restrict__ rows,
                                                  const int* __restrict__ cols, int E) {
    __shared__ int sr[128], sc[128];
    int base = blockIdx.x * 128;
    int t = threadIdx.x;
    for (int i = t; i < 128; i += 192) { int e = base + i; sr[i] = (e < E) ? rows[e] : -1; }
    for (int i = t; i < 128; i += 192) { int e = base + i; sc[i] = (e < E) ? cols[e] : -1; }
    __syncthreads();
    int sub = t % 6;
    int el  = t / 6;        // 0..31
#pragma unroll
    for (int k = 0; k < 4; k++) {
        int le = el + k * 32;
        int r = sr[le];
        int c = sc[le];
        if ((unsigned)r < NN && (unsigned)c < NN) {
            const float4 v = *(const float4*)(g_u2 + (size_t)r * 24 + sub * 4);
            red_add_v4(g_acc2 + (size_t)c * 24 + sub * 4, v.x, v.y, v.z, v.w);
        }
    }
}

// h2 = relu(dinv*(acc2+u2)+b2); nlog = relu(h2@Wn1+bn1)@Wn2+bn2;
// per-graph: max(nlog), sum(h2), cnt
__global__ __launch_bounds__(128) void k_fin2(const float* __restrict__ b2,
                                              const float* __restrict__ Wn1, const float* __restrict__ bn1,
                                              const float* __restrict__ Wn2, const float* __restrict__ bn2,
                                              const int* __restrict__ batch, int n) {
    __shared__ float W1s[24 * 16];
    __shared__ float b1s[16];
    __shared__ float W2s[16];
    __shared__ float b2s[24];
    for (int t = threadIdx.x; t < 24 * 16; t += blockDim.x) W1s[t] = Wn1[t];
    for (int t = threadIdx.x; t < 16; t += blockDim.x) { b1s[t] = bn1[t]; W2s[t] = Wn2[t]; }
    for (int t = threadIdx.x; t < 24; t += blockDim.x) b2s[t] = b2[t];
    __syncthreads();
    int i = blockIdx.x * blockDim.x + threadIdx.x;
    if (i >= n) return;
    float di = g_deg[i];
    float h[24];
    const float4* ar = (const float4*)(g_acc2 + (size_t)i * 24);
    const float4* ur = (const float4*)(g_u2  + (size_t)i * 24);
#pragma unroll
    for (int j4 = 0; j4 < 6; j4++) {
        float4 a = ar[j4], u = ur[j4];
        h[j4*4+0] = fmaxf(di * (a.x + u.x) + b2s[j4*4+0], 0.0f);
        h[j4*4+1] = fmaxf(di * (a.y + u.y) + b2s[j4*4+1], 0.0f);
        h[j4*4+2] = fmaxf(di * (a.z + u.z) + b2s[j4*4+2], 0.0f);
        h[j4*4+3] = fmaxf(di * (a.w + u.w) + b2s[j4*4+3], 0.0f);
    }
    float4* ho = (float4*)(g_h2 + (size_t)i * 24);
#pragma unroll
    for (int j4 = 0; j4 < 6; j4++)
        ho[j4] = make_float4(h[j4*4], h[j4*4+1], h[j4*4+2], h[j4*4+3]);

    float m[16];
#pragma unroll
    for (int o = 0; o < 16; o++) m[o] = b1s[o];
#pragma unroll
    for (int k = 0; k < 24; k++) {
        float v = h[k];
        const float* wr = &W1s[k * 16];
#pragma unroll
        for (int o = 0; o < 16; o++) m[o] = fmaf(v, wr[o], m[o]);
    }
    float nl = bn2[0];
#pragma unroll
    for (int o = 0; o < 16; o++) nl = fmaf(fmaxf(m[o], 0.0f), W2s[o], nl);
    g_nlog[i] = nl;

    unsigned b = (unsigned)batch[i];
    if (b < NG) {
        atomicMax(&g_gmax[b], f2ord(nl));
        atomicAdd(&g_cnt[b], 1.0f);
#pragma unroll
        for (int j = 0; j < 24; j++) atomicAdd(&g_gsum_h2[b * 24 + j], h[j]);
    }
}

// e = exp(nlog - gmax); keep in g_nlog (NOT out_n — avoids read/write race);
// accumulate per-graph sum
__global__ void k_exp(const int* __restrict__ batch, int n) {
    int i = blockIdx.x * blockDim.x + threadIdx.x;
    if (i >= n) return;
    unsigned b = (unsigned)batch[i];
    if (b >= NG) return;
    float e = __expf(g_nlog[i] - ord2f(g_gmax[b]));
    g_nlog[i] = e;
    atomicAdd(&g_gsumn[b], e);
}

// n = e / gsum; write final n; b_feat += n * h2   (thread per (node,feature))
__global__ void k_norm_bfeat(const int* __restrict__ batch, float* __restrict__ out_n, int n) {
    int t = blockIdx.x * blockDim.x + threadIdx.x;
    if (t >= n * 24) return;
    int i = t / 24, j = t % 24;
    unsigned b = (unsigned)batch[i];
    if (b >= NG) return;
    float val = g_nlog[i] / g_gsumn[b];
    if (j == 0) out_n[i] = val;
    atomicAdd(&g_bfeat[b * 24 + j], val * g_h2[(size_t)i * 24 + j]);
}

// per-graph heads: t = softmax(meanpool@Wg@Wt); bb = softmax_dim0(MLP(b_feat))
__global__ __launch_bounds__(256) void k_heads(const float* __restrict__ Wg, const float* __restrict__ bg,
                                               const float* __restrict__ Wt, const float* __restrict__ bt,
                                               const float* __restrict__ Wb1, const float* __restrict__ bb1,
                                               const float* __restrict__ Wb2, const float* __restrict__ bb2,
                                               float* __restrict__ out_t, float* __restrict__ out_bb) {
    __shared__ float sBB[NG * 3];
    __shared__ float cmax[3], csum[3];
    int b = threadIdx.x;

    // mean pool + g_fcn1 + t head
    float c = fmaxf(g_cnt[b], 1.0f);
    float g24[24];
#pragma unroll
    for (int j = 0; j < 24; j++) g24[j] = g_gsum_h2[b * 24 + j] / c;
    float t0 = bt[0], t1 = bt[1];
    for (int o = 0; o < 32; o++) {
        float go = bg[o];
#pragma unroll
        for (int k = 0; k < 24; k++) go = fmaf(g24[k], Wg[k * 32 + o], go);
        t0 = fmaf(go, Wt[o * 2 + 0], t0);
        t1 = fmaf(go, Wt[o * 2 + 1], t1);
    }
    float mx = fmaxf(t0, t1);
    float e0 = __expf(t0 - mx), e1 = __expf(t1 - mx);
    float s = e0 + e1;
    out_t[2 * b + 0] = e0 / s;
    out_t[2 * b + 1] = e1 / s;

    // bb head (pre-softmax)
    float bf[24];
#pragma unroll
    for (int k = 0; k < 24; k++) bf[k] = g_bfeat[b * 24 + k];
    float r16[16];
#pragma unroll
    for (int o = 0; o < 16; o++) {
        float v = bb1[o];
#pragma unroll
        for (int k = 0; k < 24; k++) v = fmaf(bf[k], Wb1[k * 16 + o], v);
        r16[o] = fmaxf(v, 0.0f);
    }
#pragma unroll
    for (int o = 0; o < 3; o++) {
        float v = bb2[o];
#pragma unroll
        for (int k = 0; k < 16; k++) v = fmaf(r16[k], Wb2[k * 3 + o], v);
        sBB[b * 3 + o] = v;
    }
    __syncthreads();
    if (b < 3) {
        float m = -3.4e38f;
        for (int r = 0; r < NG; r++) m = fmaxf(m, sBB[r * 3 + b]);
        float ss = 0.0f;
        for (int r = 0; r < NG; r++) ss += __expf(sBB[r * 3 + b] - m);
        cmax[b] = m; csum[b] = ss;
    }
    __syncthreads();
#pragma unroll
    for (int o = 0; o < 3; o++)
        out_bb[b * 3 + o] = __expf(sBB[b * 3 + o] - cmax[o]) / csum[o];
}

// ---------------- launcher ----------------
extern "C" void kernel_launch(void* const* d_in, const int* in_sizes, int n_in,
                              void* d_out, int out_size) {
    const float* x   = (const float*)d_in[0];
    const int*   ei  = (const int*)d_in[1];   // int32! (JAX x64 disabled)
    const int*   bat = (const int*)d_in[2];   // int32!
    const float *W1 = (const float*)d_in[3],  *b1 = (const float*)d_in[4];
    const float *W2 = (const float*)d_in[5],  *b2 = (const float*)d_in[6];
    const float *Wg = (const float*)d_in[7],  *bg = (const float*)d_in[8];
    const float *Wt = (const float*)d_in[9],  *bt = (const float*)d_in[10];
    const float *Wn1= (const float*)d_in[11], *bn1= (const float*)d_in[12];
    const float *Wn2= (const float*)d_in[13], *bn2= (const float*)d_in[14];
    const float *Wb1= (const float*)d_in[15], *bb1= (const float*)d_in[16];
    const float *Wb2= (const float*)d_in[17], *bb2= (const float*)d_in[18];

    const int N = in_sizes[0] / 32;
    const int E = in_sizes[1] / 2;
    const int* rows = ei;       // edge_index[0] = source
    const int* cols = ei + E;   // edge_index[1] = target

    float* out = (float*)d_out;
    float* out_t  = out;              // [256,2]
    float* out_n  = out + NG * 2;     // [N,1]
    float* out_bb = out + NG * 2 + N; // [256,3]

    const int TB = 256;
    k_init<<<(NN * 32 + TB - 1) / TB, TB>>>();
    k_deg<<<(E + TB - 1) / TB, TB>>>(cols, E);
    k_dinv<<<(N + TB - 1) / TB, TB>>>(N);
    k_gemm1<<<(N + 127) / 128, 128>>>(x, W1, N);
    k_scatter1<<<(E + 127) / 128, 256>>>(rows, cols, E);
    k_fin1gemm2<<<(N + 127) / 128, 128>>>(b1, W2, N);
    k_scatter2<<<(E + 127) / 128, 192>>>(rows, cols, E);
    k_fin2<<<(N + 127) / 128, 128>>>(b2, Wn1, bn1, Wn2, bn2, bat, N);
    k_exp<<<(N + TB - 1) / TB, TB>>>(bat, N);
    k_norm_bfeat<<<(N * 24 + TB - 1) / TB, TB>>>(bat, out_n, N);
    k_heads<<<1, NG>>>(Wg, bg, Wt, bt, Wb1, bb1, Wb2, bb2, out_t, out_bb);
}

// round 3
// speedup vs baseline: 1.7395x; 1.7395x over previous
#include <cuda_runtime.h>
#include <cuda_bf16.h>
#include <math.h>

// Problem constants (fixed by setup_inputs)
#define NN 100000          // nodes
#define NE 3200000         // edges
#define NG 256             // graphs
#define NB 391             // ceil(NN/256) blocks for prefix sum

// -------- scratch (static device globals; no allocation) --------
__device__ __align__(16) float g_u1  [NN * 32];   // (x@W1)*dinv
__device__ __align__(16) float g_acc1[NN * 32];   // aggregated conv1 (incl self)
__device__ __align__(16) float g_u2  [NN * 24];   // (h1@W2)*dinv
__device__ __align__(16) float g_acc2[NN * 24];   // aggregated conv2 (incl self)
__device__ __align__(16) float g_h2  [NN * 24];   // conv2 output (relu)
__device__ __align__(16) float g_nlog[NN];        // node logits -> exp values
__device__ float    g_dinv[NN];
__device__ int      g_cnti[NN];                   // in-degree histogram
__device__ int      g_off [NN + 1];               // CSR offsets
__device__ int      g_cur [NN];                   // placement cursors
__device__ int      g_srt [NE];                   // rows sorted by col
__device__ int      g_bsum[NB];                   // per-block sums
__device__ int      g_boff[NB];                   // exclusive block offsets
__device__ __align__(16) float g_gsum_h2[NG * 24];
__device__ __align__(16) float g_bfeat  [NG * 24];
__device__ float    g_cnt  [NG];
__device__ unsigned g_gmax [NG];
__device__ float    g_gsumn[NG];

// ---------------- helpers ----------------
__device__ __forceinline__ unsigned f2ord(float f) {
    unsigned u = __float_as_uint(f);
    return (u & 0x80000000u) ? ~u : (u | 0x80000000u);
}
__device__ __forceinline__ float ord2f(unsigned u) {
    return (u & 0x80000000u) ? __uint_as_float(u ^ 0x80000000u) : __uint_as_float(~u);
}
__device__ __forceinline__ float bfly24(float v) {
#pragma unroll
    for (int d = 16; d >= 1; d >>= 1) v += __shfl_xor_sync(0xffffffffu, v, d);
    return v;
}

// ---------------- kernels ----------------

// zero small scratch (runs every launch; graph-replay safe)
__global__ void k_init(int n) {
    int i = blockIdx.x * blockDim.x + threadIdx.x;
    if (i < NN) g_cnti[i] = 0;
    if (i < NG * 24) { g_gsum_h2[i] = 0.0f; g_bfeat[i] = 0.0f; }
    if (i < NG) { g_cnt[i] = 0.0f; g_gmax[i] = 0u; g_gsumn[i] = 0.0f; }
}

// in-degree histogram over targets (edge_index is int32 — JAX x64 disabled)
__global__ void k_hist(const int* __restrict__ cols, int E) {
    int e = blockIdx.x * blockDim.x + threadIdx.x;
    if (e < E) {
        unsigned c = (unsigned)cols[e];
        if (c < NN) atomicAdd(&g_cnti[c], 1);
    }
}

__global__ void k_dinv(int n) {
    int i = blockIdx.x * blockDim.x + threadIdx.x;
    if (i < n) g_dinv[i] = rsqrtf((float)(g_cnti[i] + 1));   // +1 self loop
}

// per-256-block sums of histogram
__global__ __launch_bounds__(256) void k_blocksum() {
    __shared__ int s[256];
    int i = blockIdx.x * 256 + threadIdx.x;
    s[threadIdx.x] = (i < NN) ? g_cnti[i] : 0;
    __syncthreads();
#pragma unroll
    for (int d = 128; d >= 1; d >>= 1) {
        if (threadIdx.x < d) s[threadIdx.x] += s[threadIdx.x + d];
        __syncthreads();
    }
    if (threadIdx.x == 0) g_bsum[blockIdx.x] = s[0];
}

// single-block exclusive scan of NB block sums
__global__ __launch_bounds__(512) void k_scanb(int E) {
    __shared__ int s[512];
    int t = threadIdx.x;
    int v = (t < NB) ? g_bsum[t] : 0;
    s[t] = v;
    __syncthreads();
#pragma unroll
    for (int d = 1; d < 512; d <<= 1) {
        int x = (t >= d) ? s[t - d] : 0;
        __syncthreads();
        s[t] += x;
        __syncthreads();
    }
    if (t < NB) g_boff[t] = s[t] - v;      // exclusive
    if (t == 0) g_off[NN] = E;
}

// per-block exclusive scan -> CSR offsets + cursors
__global__ __launch_bounds__(256) void k_offsets() {
    __shared__ int s[256];
    int t = threadIdx.x;
    int i = blockIdx.x * 256 + t;
    int v = (i < NN) ? g_cnti[i] : 0;
    s[t] = v;
    __syncthreads();
#pragma unroll
    for (int d = 1; d < 256; d <<= 1) {
        int x = (t >= d) ? s[t - d] : 0;
        __syncthreads();
        s[t] += x;
        __syncthreads();
    }
    if (i < NN) {
        int o = g_boff[blockIdx.x] + s[t] - v;
        g_off[i] = o;
        g_cur[i] = o;
    }
}

// place rows into CSR order (sorted by target col)
__global__ void k_place(const int* __restrict__ rows, const int* __restrict__ cols, int E) {
    int e = blockIdx.x * blockDim.x + threadIdx.x;
    if (e < E) {
        unsigned c = (unsigned)cols[e];
        unsigned r = (unsigned)rows[e];
        if (c < NN && r < NN) {
            int p = atomicAdd(&g_cur[c], 1);
            g_srt[p] = (int)r;
        }
    }
}

// u1 = (x @ W1) * dinv   [NN,32]
__global__ __launch_bounds__(256) void k_gemm1(const float* __restrict__ x,
                                               const float* __restrict__ W1, int n) {
    __shared__ float Ws[32 * 32];
    for (int t = threadIdx.x; t < 1024; t += blockDim.x) Ws[t] = W1[t];
    __syncthreads();
    int i = blockIdx.x * blockDim.x + threadIdx.x;
    if (i >= n) return;
    float a[32];
#pragma unroll
    for (int j = 0; j < 32; j++) a[j] = 0.0f;
    const float4* xr = (const float4*)(x + (size_t)i * 32);
#pragma unroll
    for (int k4 = 0; k4 < 8; k4++) {
        float4 xv = xr[k4];
        float xs[4] = {xv.x, xv.y, xv.z, xv.w};
#pragma unroll
        for (int c = 0; c < 4; c++) {
            float v = xs[c];
            const float* wr = &Ws[(k4 * 4 + c) * 32];
#pragma unroll
            for (int j = 0; j < 32; j++) a[j] = fmaf(v, wr[j], a[j]);
        }
    }
    float di = g_dinv[i];
    float4* out = (float4*)(g_u1 + (size_t)i * 32);
#pragma unroll
    for (int j4 = 0; j4 < 8; j4++)
        out[j4] = make_float4(a[j4*4]*di, a[j4*4+1]*di, a[j4*4+2]*di, a[j4*4+3]*di);
}

// aggregate conv1: acc1[i] = u1[i] + sum_{r in nbr(i)} u1[r]   (8 thr/node)
__global__ __launch_bounds__(256) void k_aggr1(int n) {
    int node = blockIdx.x * 32 + (threadIdx.x >> 3);
    int sub  = threadIdx.x & 7;
    if (node >= n) return;
    int s = g_off[node], e = g_off[node + 1];
    float4 acc = *(const float4*)(g_u1 + (size_t)node * 32 + sub * 4);  // self loop
#pragma unroll 4
    for (int j = s; j < e; j++) {
        int r = g_srt[j];
        float4 v = *(const float4*)(g_u1 + (size_t)r * 32 + sub * 4);
        acc.x += v.x; acc.y += v.y; acc.z += v.z; acc.w += v.w;
    }
    *(float4*)(g_acc1 + (size_t)node * 32 + sub * 4) = acc;
}

// h1 = relu(dinv*acc1+b1); u2 = (h1@W2)*dinv   [NN,24]
__global__ __launch_bounds__(128) void k_fin1gemm2(const float* __restrict__ b1,
                                                   const float* __restrict__ W2, int n) {
    __shared__ float Ws[32 * 24];
    __shared__ float bs[32];
    for (int t = threadIdx.x; t < 32 * 24; t += blockDim.x) Ws[t] = W2[t];
    for (int t = threadIdx.x; t < 32; t += blockDim.x) bs[t] = b1[t];
    __syncthreads();
    int i = blockIdx.x * blockDim.x + threadIdx.x;
    if (i >= n) return;
    float di = g_dinv[i];
    float h[32];
    const float4* ar = (const float4*)(g_acc1 + (size_t)i * 32);
#pragma unroll
    for (int j4 = 0; j4 < 8; j4++) {
        float4 a = ar[j4];
        h[j4*4+0] = fmaxf(di * a.x + bs[j4*4+0], 0.0f);
        h[j4*4+1] = fmaxf(di * a.y + bs[j4*4+1], 0.0f);
        h[j4*4+2] = fmaxf(di * a.z + bs[j4*4+2], 0.0f);
        h[j4*4+3] = fmaxf(di * a.w + bs[j4*4+3], 0.0f);
    }
    float a[24];
#pragma unroll
    for (int j = 0; j < 24; j++) a[j] = 0.0f;
#pragma unroll
    for (int k = 0; k < 32; k++) {
        float v = h[k];
        const float* wr = &Ws[k * 24];
#pragma unroll
        for (int j = 0; j < 24; j++) a[j] = fmaf(v, wr[j], a[j]);
    }
    float4* out = (float4*)(g_u2 + (size_t)i * 24);
#pragma unroll
    for (int j4 = 0; j4 < 6; j4++)
        out[j4] = make_float4(a[j4*4]*di, a[j4*4+1]*di, a[j4*4+2]*di, a[j4*4+3]*di);
}

// aggregate conv2: acc2[i] = u2[i] + sum u2[r]   (6 thr/node, block 192)
__global__ __launch_bounds__(192) void k_aggr2(int n) {
    int node = blockIdx.x * 32 + (threadIdx.x / 6);
    int sub  = threadIdx.x % 6;
    if (node >= n || threadIdx.x >= 192) return;
    int s = g_off[node], e = g_off[node + 1];
    float4 acc = *(const float4*)(g_u2 + (size_t)node * 24 + sub * 4);  // self loop
#pragma unroll 4
    for (int j = s; j < e; j++) {
        int r = g_srt[j];
        float4 v = *(const float4*)(g_u2 + (size_t)r * 24 + sub * 4);
        acc.x += v.x; acc.y += v.y; acc.z += v.z; acc.w += v.w;
    }
    *(float4*)(g_acc2 + (size_t)node * 24 + sub * 4) = acc;
}

// h2 = relu(dinv*acc2+b2); nlog = relu(h2@Wn1+bn1)@Wn2+bn2;
// per-graph: max(nlog), sum(h2), cnt — warp-segmented reduction (batch sorted)
__global__ __launch_bounds__(128) void k_fin2(const float* __restrict__ b2,
                                              const float* __restrict__ Wn1, const float* __restrict__ bn1,
                                              const float* __restrict__ Wn2, const float* __restrict__ bn2,
                                              const int* __restrict__ batch, int n) {
    __shared__ float W1s[24 * 16];
    __shared__ float b1s[16];
    __shared__ float W2s[16];
    __shared__ float b2s[24];
    for (int t = threadIdx.x; t < 24 * 16; t += blockDim.x) W1s[t] = Wn1[t];
    for (int t = threadIdx.x; t < 16; t += blockDim.x) { b1s[t] = bn1[t]; W2s[t] = Wn2[t]; }
    for (int t = threadIdx.x; t < 24; t += blockDim.x) b2s[t] = b2[t];
    __syncthreads();
    int i = blockIdx.x * blockDim.x + threadIdx.x;
    bool valid = (i < n);

    float h[24];
    float nl = 0.0f;
    unsigned b = 0xffffffffu;
    if (valid) {
        float di = g_dinv[i];
        const float4* ar = (const float4*)(g_acc2 + (size_t)i * 24);
#pragma unroll
        for (int j4 = 0; j4 < 6; j4++) {
            float4 a = ar[j4];
            h[j4*4+0] = fmaxf(di * a.x + b2s[j4*4+0], 0.0f);
            h[j4*4+1] = fmaxf(di * a.y + b2s[j4*4+1], 0.0f);
            h[j4*4+2] = fmaxf(di * a.z + b2s[j4*4+2], 0.0f);
            h[j4*4+3] = fmaxf(di * a.w + b2s[j4*4+3], 0.0f);
        }
        float4* ho = (float4*)(g_h2 + (size_t)i * 24);
#pragma unroll
        for (int j4 = 0; j4 < 6; j4++)
            ho[j4] = make_float4(h[j4*4], h[j4*4+1], h[j4*4+2], h[j4*4+3]);

        float m[16];
#pragma unroll
        for (int o = 0; o < 16; o++) m[o] = b1s[o];
#pragma unroll
        for (int k = 0; k < 24; k++) {
            float v = h[k];
            const float* wr = &W1s[k * 16];
#pragma unroll
            for (int o = 0; o < 16; o++) m[o] = fmaf(v, wr[o], m[o]);
        }
        nl = bn2[0];
#pragma unroll
        for (int o = 0; o < 16; o++) nl = fmaf(fmaxf(m[o], 0.0f), W2s[o], nl);
        g_nlog[i] = nl;
        b = (unsigned)batch[i];
    } else {
#pragma unroll
        for (int j = 0; j < 24; j++) h[j] = 0.0f;
    }

    unsigned mask = __match_any_sync(0xffffffffu, b);
    int lane = threadIdx.x & 31;
    if (mask == 0xffffffffu && valid) {
        // whole warp same graph: butterfly reduce, one atomic set per warp
        float mx = nl;
#pragma unroll
        for (int d = 16; d >= 1; d >>= 1) mx = fmaxf(mx, __shfl_xor_sync(0xffffffffu, mx, d));
#pragma unroll
        for (int j = 0; j < 24; j++) {
            float v = bfly24(h[j]);
            if (lane == j) atomicAdd(&g_gsum_h2[b * 24 + j], v);  // lanes 0..23 each do one
        }
        if (lane == 24) atomicAdd(&g_cnt[b], 32.0f);
        if (lane == 25) atomicMax(&g_gmax[b], f2ord(mx));
    } else if (valid && b < NG) {
        atomicMax(&g_gmax[b], f2ord(nl));
        atomicAdd(&g_cnt[b], 1.0f);
#pragma unroll
        for (int j = 0; j < 24; j++) atomicAdd(&g_gsum_h2[b * 24 + j], h[j]);
    }
}

// e = exp(nlog - gmax); keep in g_nlog; accumulate per-graph sum (warp-segmented)
__global__ void k_exp(const int* __restrict__ batch, int n) {
    int i = blockIdx.x * blockDim.x + threadIdx.x;
    bool valid = (i < n);
    unsigned b = 0xffffffffu;
    float e = 0.0f;
    if (valid) {
        b = (unsigned)batch[i];
        e = __expf(g_nlog[i] - ord2f(g_gmax[b]));
        g_nlog[i] = e;
    }
    unsigned mask = __match_any_sync(0xffffffffu, b);
    int lane = threadIdx.x & 31;
    if (mask == 0xffffffffu && valid) {
        float s = bfly24(e);
        if (lane == 0) atomicAdd(&g_gsumn[b], s);
    } else if (valid && b < NG) {
        atomicAdd(&g_gsumn[b], e);
    }
}

// n = e / gsum; write final n; bfeat[b] += n * h2[i]  (node per thread, warp-segmented)
__global__ void k_nbf(const int* __restrict__ batch, float* __restrict__ out_n, int n) {
    int i = blockIdx.x * blockDim.x + threadIdx.x;
    bool valid = (i < n);
    unsigned b = 0xffffffffu;
    float val = 0.0f;
    float h[24];
    if (valid) {
        b = (unsigned)batch[i];
        val = g_nlog[i] / g_gsumn[b];
        out_n[i] = val;
        const float4* hr = (const float4*)(g_h2 + (size_t)i * 24);
#pragma unroll
        for (int j4 = 0; j4 < 6; j4++) {
            float4 v = hr[j4];
            h[j4*4+0] = v.x; h[j4*4+1] = v.y; h[j4*4+2] = v.z; h[j4*4+3] = v.w;
        }
    } else {
#pragma unroll
        for (int j = 0; j < 24; j++) h[j] = 0.0f;
    }
    unsigned mask = __match_any_sync(0xffffffffu, b);
    int lane = threadIdx.x & 31;
    if (mask == 0xffffffffu && valid) {
#pragma unroll
        for (int j = 0; j < 24; j++) {
            float v = bfly24(val * h[j]);
            if (lane == j) atomicAdd(&g_bfeat[b * 24 + j], v);
        }
    } else if (valid && b < NG) {
#pragma unroll
        for (int j = 0; j < 24; j++) atomicAdd(&g_bfeat[b * 24 + j], val * h[j]);
    }
}

// per-graph heads: t = softmax(meanpool@Wg@Wt); bb = softmax_dim0(MLP(b_feat))
__global__ __launch_bounds__(256) void k_heads(const float* __restrict__ Wg, const float* __restrict__ bg,
                                               const float* __restrict__ Wt, const float* __restrict__ bt,
                                               const float* __restrict__ Wb1, const float* __restrict__ bb1,
                                               const float* __restrict__ Wb2, const float* __restrict__ bb2,
                                               float* __restrict__ out_t, float* __restrict__ out_bb) {
    __shared__ float sBB[NG * 3];
    __shared__ float cmax[3], csum[3];
    int b = threadIdx.x;

    float c = fmaxf(g_cnt[b], 1.0f);
    float g24[24];
#pragma unroll
    for (int j = 0; j < 24; j++) g24[j] = g_gsum_h2[b * 24 + j] / c;
    float t0 = bt[0], t1 = bt[1];
    for (int o = 0; o < 32; o++) {
        float go = bg[o];
#pragma unroll
        for (int k = 0; k < 24; k++) go = fmaf(g24[k], Wg[k * 32 + o], go);
        t0 = fmaf(go, Wt[o * 2 + 0], t0);
        t1 = fmaf(go, Wt[o * 2 + 1], t1);
    }
    float mx = fmaxf(t0, t1);
    float e0 = __expf(t0 - mx), e1 = __expf(t1 - mx);
    float s = e0 + e1;
    out_t[2 * b + 0] = e0 / s;
    out_t[2 * b + 1] = e1 / s;

    float bf[24];
#pragma unroll
    for (int k = 0; k < 24; k++) bf[k] = g_bfeat[b * 24 + k];
    float r16[16];
#pragma unroll
    for (int o = 0; o < 16; o++) {
        float v = bb1[o];
#pragma unroll
        for (int k = 0; k < 24; k++) v = fmaf(bf[k], Wb1[k * 16 + o], v);
        r16[o] = fmaxf(v, 0.0f);
    }
#pragma unroll
    for (int o = 0; o < 3; o++) {
        float v = bb2[o];
#pragma unroll
        for (int k = 0; k < 16; k++) v = fmaf(r16[k], Wb2[k * 3 + o], v);
        sBB[b * 3 + o] = v;
    }
    __syncthreads();
    if (b < 3) {
        float m = -3.4e38f;
        for (int r = 0; r < NG; r++) m = fmaxf(m, sBB[r * 3 + b]);
        float ss = 0.0f;
        for (int r = 0; r < NG; r++) ss += __expf(sBB[r * 3 + b] - m);
        cmax[b] = m; csum[b] = ss;
    }
    __syncthreads();
#pragma unroll
    for (int o = 0; o < 3; o++)
        out_bb[b * 3 + o] = __expf(sBB[b * 3 + o] - cmax[o]) / csum[o];
}

// ---------------- launcher ----------------
extern "C" void kernel_launch(void* const* d_in, const int* in_sizes, int n_in,
                              void* d_out, int out_size) {
    const float* x   = (const float*)d_in[0];
    const int*   ei  = (const int*)d_in[1];
    const int*   bat = (const int*)d_in[2];
    const float *W1 = (const float*)d_in[3],  *b1 = (const float*)d_in[4];
    const float *W2 = (const float*)d_in[5];
    const float *b2 = (const float*)d_in[6];
    const float *Wg = (const float*)d_in[7],  *bg = (const float*)d_in[8];
    const float *Wt = (const float*)d_in[9],  *bt = (const float*)d_in[10];
    const float *Wn1= (const float*)d_in[11], *bn1= (const float*)d_in[12];
    const float *Wn2= (const float*)d_in[13], *bn2= (const float*)d_in[14];
    const float *Wb1= (const float*)d_in[15], *bb1= (const float*)d_in[16];
    const float *Wb2= (const float*)d_in[17], *bb2= (const float*)d_in[18];

    const int N = in_sizes[0] / 32;
    const int E = in_sizes[1] / 2;
    const int* rows = ei;       // edge_index[0] = source
    const int* cols = ei + E;   // edge_index[1] = target

    float* out = (float*)d_out;
    float* out_t  = out;              // [256,2]
    float* out_n  = out + NG * 2;     // [N,1]
    float* out_bb = out + NG * 2 + N; // [256,3]

    const int TB = 256;
    k_init<<<(NN + TB - 1) / TB, TB>>>(N);
    k_hist<<<(E + TB - 1) / TB, TB>>>(cols, E);
    k_dinv<<<(N + TB - 1) / TB, TB>>>(N);
    k_blocksum<<<NB, 256>>>();
    k_scanb<<<1, 512>>>(E);
    k_offsets<<<NB, 256>>>();
    k_place<<<(E + TB - 1) / TB, TB>>>(rows, cols, E);
    k_gemm1<<<(N + 255) / 256, 256>>>(x, W1, N);
    k_aggr1<<<(N + 31) / 32, 256>>>(N);
    k_fin1gemm2<<<(N + 127) / 128, 128>>>(b1, W2, N);
    k_aggr2<<<(N + 31) / 32, 192>>>(N);
    k_fin2<<<(N + 127) / 128, 128>>>(b2, Wn1, bn1, Wn2, bn2, bat, N);
    k_exp<<<(N + TB - 1) / TB, TB>>>(bat, N);
    k_nbf<<<(N + TB - 1) / TB, TB>>>(bat, out_n, N);
    k_heads<<<1, NG>>>(Wg, bg, Wt, bt, Wb1, bb1, Wb2, bb2, out_t, out_bb);
}

// round 4
// speedup vs baseline: 1.7718x; 1.0185x over previous
#include <cuda_runtime.h>
#include <cuda_bf16.h>
#include <math.h>

// Problem constants (fixed by setup_inputs)
#define NN 100000          // nodes
#define NE 3200000         // edges
#define NG 256             // graphs
#define NB 391             // ceil(NN/256)

// -------- scratch (static device globals; no allocation) --------
__device__ __align__(16) float g_u1  [NN * 32];
__device__ __align__(16) float g_acc1[NN * 32];
__device__ __align__(16) float g_u2  [NN * 24];
__device__ __align__(16) float g_acc2[NN * 24];
__device__ __align__(16) float g_h2  [NN * 24];
__device__ __align__(16) float g_nlog[NN];
__device__ float    g_dinv[NN];
__device__ int      g_cnti[NN];      // in-degree histogram (self-cleaned in k_offsets)
__device__ int      g_off [NN + 1];
__device__ int      g_cur [NN];
__device__ int      g_srt [NE];
__device__ int      g_bsum[NB];
__device__ int      g_boff[NB];
__device__ __align__(16) float g_gsum_h2[NG * 24];
__device__ __align__(16) float g_bfeat  [NG * 24];
__device__ float    g_cnt  [NG];
__device__ unsigned g_gmax [NG];
__device__ float    g_gsumn[NG];

// ---------------- helpers ----------------
__device__ __forceinline__ unsigned f2ord(float f) {
    unsigned u = __float_as_uint(f);
    return (u & 0x80000000u) ? ~u : (u | 0x80000000u);
}
__device__ __forceinline__ float ord2f(unsigned u) {
    return (u & 0x80000000u) ? __uint_as_float(u ^ 0x80000000u) : __uint_as_float(~u);
}
__device__ __forceinline__ float bfly24(float v) {
#pragma unroll
    for (int d = 16; d >= 1; d >>= 1) v += __shfl_xor_sync(0xffffffffu, v, d);
    return v;
}

// ---------------- kernels ----------------

// zero small per-graph scratch only (g_cnti self-cleans in k_offsets)
__global__ void k_init() {
    int i = blockIdx.x * blockDim.x + threadIdx.x;
    if (i < NG * 24) { g_gsum_h2[i] = 0.0f; g_bfeat[i] = 0.0f; }
    if (i < NG) { g_cnt[i] = 0.0f; g_gmax[i] = 0u; g_gsumn[i] = 0.0f; }
}

// in-degree histogram, 2 edges / thread (edge_index is int32 — JAX x64 disabled)
__global__ void k_hist(const int* __restrict__ cols, int E) {
    int e = (blockIdx.x * blockDim.x + threadIdx.x) * 2;
    if (e + 1 < E) {
        int2 c = *(const int2*)(cols + e);
        if ((unsigned)c.x < NN) atomicAdd(&g_cnti[c.x], 1);
        if ((unsigned)c.y < NN) atomicAdd(&g_cnti[c.y], 1);
    } else if (e < E) {
        unsigned c = (unsigned)cols[e];
        if (c < NN) atomicAdd(&g_cnti[c], 1);
    }
}

// per-256-block sums of histogram
__global__ __launch_bounds__(256) void k_blocksum() {
    __shared__ int s[256];
    int i = blockIdx.x * 256 + threadIdx.x;
    s[threadIdx.x] = (i < NN) ? g_cnti[i] : 0;
    __syncthreads();
#pragma unroll
    for (int d = 128; d >= 32; d >>= 1) {
        if (threadIdx.x < d) s[threadIdx.x] += s[threadIdx.x + d];
        __syncthreads();
    }
    if (threadIdx.x < 32) {
        int v = s[threadIdx.x];
#pragma unroll
        for (int d = 16; d >= 1; d >>= 1) v += __shfl_xor_sync(0xffffffffu, v, d);
        if (threadIdx.x == 0) g_bsum[blockIdx.x] = v;
    }
}

// single-block exclusive scan of NB block sums
__global__ __launch_bounds__(512) void k_scanb(int E) {
    __shared__ int s[512];
    int t = threadIdx.x;
    int v = (t < NB) ? g_bsum[t] : 0;
    s[t] = v;
    __syncthreads();
#pragma unroll
    for (int d = 1; d < 512; d <<= 1) {
        int x = (t >= d) ? s[t - d] : 0;
        __syncthreads();
        s[t] += x;
        __syncthreads();
    }
    if (t < NB) g_boff[t] = s[t] - v;      // exclusive
    if (t == 0) g_off[NN] = E;
}

// per-block exclusive scan -> CSR offsets + cursors; also dinv; self-clean cnti
__global__ __launch_bounds__(256) void k_offsets() {
    __shared__ int s[256];
    int t = threadIdx.x;
    int i = blockIdx.x * 256 + t;
    int v = (i < NN) ? g_cnti[i] : 0;
    s[t] = v;
    __syncthreads();
#pragma unroll
    for (int d = 1; d < 256; d <<= 1) {
        int x = (t >= d) ? s[t - d] : 0;
        __syncthreads();
        s[t] += x;
        __syncthreads();
    }
    if (i < NN) {
        int o = g_boff[blockIdx.x] + s[t] - v;
        g_off[i] = o;
        g_cur[i] = o;
        g_dinv[i] = rsqrtf((float)(v + 1));   // +1 self loop
        g_cnti[i] = 0;                        // self-clean for next replay
    }
}

// place rows into CSR order (sorted by target col), 2 edges / thread
__global__ void k_place(const int* __restrict__ rows, const int* __restrict__ cols, int E) {
    int e = (blockIdx.x * blockDim.x + threadIdx.x) * 2;
    if (e + 1 < E) {
        int2 r = *(const int2*)(rows + e);
        int2 c = *(const int2*)(cols + e);
        if ((unsigned)c.x < NN && (unsigned)r.x < NN) g_srt[atomicAdd(&g_cur[c.x], 1)] = r.x;
        if ((unsigned)c.y < NN && (unsigned)r.y < NN) g_srt[atomicAdd(&g_cur[c.y], 1)] = r.y;
    } else if (e < E) {
        unsigned c = (unsigned)cols[e], r = (unsigned)rows[e];
        if (c < NN && r < NN) g_srt[atomicAdd(&g_cur[c], 1)] = (int)r;
    }
}

// u1 = (x @ W1) * dinv, smem-staged tiles  [NN,32]
__global__ __launch_bounds__(256) void k_gemm1(const float* __restrict__ x,
                                               const float* __restrict__ W1, int n) {
    __shared__ float4 Ws[32 * 8];          // W1 as float4 rows
    __shared__ float4 st[256 * 9];         // tile, pitch 9 float4 (odd => no LDS.128 conflicts)
    for (int t = threadIdx.x; t < 256; t += 256) Ws[t] = ((const float4*)W1)[t];
    int base = blockIdx.x * 256;
    int nrows = n - base; if (nrows > 256) nrows = 256;
    const float4* xg = (const float4*)x + (size_t)base * 8;
    for (int idx = threadIdx.x; idx < 2048; idx += 256) {
        int row = idx >> 3, c4 = idx & 7;
        if (row < nrows) st[row * 9 + c4] = xg[idx];
    }
    __syncthreads();
    int tid = threadIdx.x;
    bool valid = tid < nrows;
    float a[32];
    if (valid) {
        float4 xv[8];
#pragma unroll
        for (int k4 = 0; k4 < 8; k4++) xv[k4] = st[tid * 9 + k4];
#pragma unroll
        for (int j = 0; j < 32; j++) a[j] = 0.0f;
#pragma unroll
        for (int k4 = 0; k4 < 8; k4++) {
            float xs[4] = {xv[k4].x, xv[k4].y, xv[k4].z, xv[k4].w};
#pragma unroll
            for (int c = 0; c < 4; c++) {
                float v = xs[c];
                int k = k4 * 4 + c;
#pragma unroll
                for (int j4 = 0; j4 < 8; j4++) {
                    float4 w = Ws[k * 8 + j4];
                    a[j4*4+0] = fmaf(v, w.x, a[j4*4+0]);
                    a[j4*4+1] = fmaf(v, w.y, a[j4*4+1]);
                    a[j4*4+2] = fmaf(v, w.z, a[j4*4+2]);
                    a[j4*4+3] = fmaf(v, w.w, a[j4*4+3]);
                }
            }
        }
    }
    __syncthreads();
    if (valid) {
        float di = g_dinv[base + tid];
#pragma unroll
        for (int j4 = 0; j4 < 8; j4++)
            st[tid * 9 + j4] = make_float4(a[j4*4]*di, a[j4*4+1]*di, a[j4*4+2]*di, a[j4*4+3]*di);
    }
    __syncthreads();
    float4* og = (float4*)g_u1 + (size_t)base * 8;
    for (int idx = threadIdx.x; idx < 2048; idx += 256) {
        int row = idx >> 3, c4 = idx & 7;
        if (row < nrows) og[idx] = st[row * 9 + c4];
    }
}

// aggregate conv1: acc1[i] = u1[i] + sum nbr u1[r]   (8 thr/node, MLP-4 prefetch)
__global__ __launch_bounds__(256) void k_aggr1(int n) {
    int node = blockIdx.x * 32 + (threadIdx.x >> 3);
    int sub  = threadIdx.x & 7;
    if (node >= n) return;
    int s = g_off[node], e = g_off[node + 1];
    const float4* U = (const float4*)g_u1;
    float4 acc = U[node * 8 + sub];    // self loop
    float4 acc2 = make_float4(0.f, 0.f, 0.f, 0.f);
    int j = s;
    for (; j + 4 <= e; j += 4) {
        int r0 = g_srt[j], r1 = g_srt[j+1], r2 = g_srt[j+2], r3 = g_srt[j+3];
        float4 v0 = U[r0 * 8 + sub];
        float4 v1 = U[r1 * 8 + sub];
        float4 v2 = U[r2 * 8 + sub];
        float4 v3 = U[r3 * 8 + sub];
        acc.x  += v0.x + v1.x; acc.y  += v0.y + v1.y; acc.z  += v0.z + v1.z; acc.w  += v0.w + v1.w;
        acc2.x += v2.x + v3.x; acc2.y += v2.y + v3.y; acc2.z += v2.z + v3.z; acc2.w += v2.w + v3.w;
    }
    for (; j < e; j++) {
        int r = g_srt[j];
        float4 v = U[r * 8 + sub];
        acc.x += v.x; acc.y += v.y; acc.z += v.z; acc.w += v.w;
    }
    acc.x += acc2.x; acc.y += acc2.y; acc.z += acc2.z; acc.w += acc2.w;
    ((float4*)g_acc1)[node * 8 + sub] = acc;
}

// h1 = relu(dinv*acc1+b1); u2 = (h1@W2)*dinv, smem-staged   [NN,24]
__global__ __launch_bounds__(256) void k_fin1gemm2(const float* __restrict__ b1,
                                                   const float* __restrict__ W2, int n) {
    __shared__ float4 Ws[32 * 6];          // W2 rows as 6 float4
    __shared__ float  bs[32];
    __shared__ float4 st[256 * 9];
    for (int t = threadIdx.x; t < 192; t += 256) Ws[t] = ((const float4*)W2)[t];
    if (threadIdx.x < 32) bs[threadIdx.x] = b1[threadIdx.x];
    int base = blockIdx.x * 256;
    int nrows = n - base; if (nrows > 256) nrows = 256;
    const float4* ag = (const float4*)g_acc1 + (size_t)base * 8;
    for (int idx = threadIdx.x; idx < 2048; idx += 256) {
        int row = idx >> 3, c4 = idx & 7;
        if (row < nrows) st[row * 9 + c4] = ag[idx];
    }
    __syncthreads();
    int tid = threadIdx.x;
    bool valid = tid < nrows;
    float a[24];
    float di = 0.0f;
    if (valid) {
        di = g_dinv[base + tid];
        float4 av[8];
#pragma unroll
        for (int k4 = 0; k4 < 8; k4++) av[k4] = st[tid * 9 + k4];
#pragma unroll
        for (int j = 0; j < 24; j++) a[j] = 0.0f;
#pragma unroll
        for (int k4 = 0; k4 < 8; k4++) {
            float hs[4];
            hs[0] = fmaxf(di * av[k4].x + bs[k4*4+0], 0.0f);
            hs[1] = fmaxf(di * av[k4].y + bs[k4*4+1], 0.0f);
            hs[2] = fmaxf(di * av[k4].z + bs[k4*4+2], 0.0f);
            hs[3] = fmaxf(di * av[k4].w + bs[k4*4+3], 0.0f);
#pragma unroll
            for (int c = 0; c < 4; c++) {
                float v = hs[c];
                int k = k4 * 4 + c;
#pragma unroll
                for (int j4 = 0; j4 < 6; j4++) {
                    float4 w = Ws[k * 6 + j4];
                    a[j4*4+0] = fmaf(v, w.x, a[j4*4+0]);
                    a[j4*4+1] = fmaf(v, w.y, a[j4*4+1]);
                    a[j4*4+2] = fmaf(v, w.z, a[j4*4+2]);
                    a[j4*4+3] = fmaf(v, w.w, a[j4*4+3]);
                }
            }
        }
    }
    __syncthreads();
    if (valid) {
#pragma unroll
        for (int j4 = 0; j4 < 6; j4++)
            st[tid * 7 + j4] = make_float4(a[j4*4]*di, a[j4*4+1]*di, a[j4*4+2]*di, a[j4*4+3]*di);
    }
    __syncthreads();
    float4* og = (float4*)g_u2 + (size_t)base * 6;
    for (int idx = threadIdx.x; idx < 1536; idx += 256) {
        int row = idx / 6, c4 = idx % 6;
        if (row < nrows) og[idx] = st[row * 7 + c4];
    }
}

// aggregate conv2: acc2[i] = u2[i] + sum u2[r]   (6 thr/node, MLP-4)
__global__ __launch_bounds__(192) void k_aggr2(int n) {
    int node = blockIdx.x * 32 + (threadIdx.x / 6);
    int sub  = threadIdx.x % 6;
    if (node >= n) return;
    int s = g_off[node], e = g_off[node + 1];
    const float4* U = (const float4*)g_u2;
    float4 acc = U[node * 6 + sub];    // self loop
    float4 acc2 = make_float4(0.f, 0.f, 0.f, 0.f);
    int j = s;
    for (; j + 4 <= e; j += 4) {
        int r0 = g_srt[j], r1 = g_srt[j+1], r2 = g_srt[j+2], r3 = g_srt[j+3];
        float4 v0 = U[r0 * 6 + sub];
        float4 v1 = U[r1 * 6 + sub];
        float4 v2 = U[r2 * 6 + sub];
        float4 v3 = U[r3 * 6 + sub];
        acc.x  += v0.x + v1.x; acc.y  += v0.y + v1.y; acc.z  += v0.z + v1.z; acc.w  += v0.w + v1.w;
        acc2.x += v2.x + v3.x; acc2.y += v2.y + v3.y; acc2.z += v2.z + v3.z; acc2.w += v2.w + v3.w;
    }
    for (; j < e; j++) {
        int r = g_srt[j];
        float4 v = U[r * 6 + sub];
        acc.x += v.x; acc.y += v.y; acc.z += v.z; acc.w += v.w;
    }
    acc.x += acc2.x; acc.y += acc2.y; acc.z += acc2.z; acc.w += acc2.w;
    ((float4*)g_acc2)[node * 6 + sub] = acc;
}

// h2 = relu(dinv*acc2+b2); nlog = relu(h2@Wn1+bn1)@Wn2+bn2; per-graph reductions
__global__ __launch_bounds__(256) void k_fin2(const float* __restrict__ b2,
                                              const float* __restrict__ Wn1, const float* __restrict__ bn1,
                                              const float* __restrict__ Wn2, const float* __restrict__ bn2,
                                              const int* __restrict__ batch, int n) {
    __shared__ float4 W1s[24 * 4];         // Wn1 rows as 4 float4
    __shared__ float  b1s[16];
    __shared__ float  W2s[16];
    __shared__ float  b2s[24];
    __shared__ float4 st[256 * 7];
    for (int t = threadIdx.x; t < 96; t += 256) W1s[t] = ((const float4*)Wn1)[t];
    if (threadIdx.x < 16) { b1s[threadIdx.x] = bn1[threadIdx.x]; W2s[threadIdx.x] = Wn2[threadIdx.x]; }
    if (threadIdx.x < 24) b2s[threadIdx.x] = b2[threadIdx.x];
    int base = blockIdx.x * 256;
    int nrows = n - base; if (nrows > 256) nrows = 256;
    const float4* ag = (const float4*)g_acc2 + (size_t)base * 6;
    for (int idx = threadIdx.x; idx < 1536; idx += 256) {
        int row = idx / 6, c4 = idx % 6;
        if (row < nrows) st[row * 7 + c4] = ag[idx];
    }
    __syncthreads();
    int tid = threadIdx.x;
    int i = base + tid;
    bool valid = tid < nrows;
    float h[24];
    float nl = 0.0f;
    unsigned b = 0xffffffffu;
    if (valid) {
        float di = g_dinv[i];
#pragma unroll
        for (int j4 = 0; j4 < 6; j4++) {
            float4 a = st[tid * 7 + j4];
            h[j4*4+0] = fmaxf(di * a.x + b2s[j4*4+0], 0.0f);
            h[j4*4+1] = fmaxf(di * a.y + b2s[j4*4+1], 0.0f);
            h[j4*4+2] = fmaxf(di * a.z + b2s[j4*4+2], 0.0f);
            h[j4*4+3] = fmaxf(di * a.w + b2s[j4*4+3], 0.0f);
        }
        float m[16];
#pragma unroll
        for (int o = 0; o < 16; o++) m[o] = b1s[o];
#pragma unroll
        for (int k = 0; k < 24; k++) {
            float v = h[k];
#pragma unroll
            for (int o4 = 0; o4 < 4; o4++) {
                float4 w = W1s[k * 4 + o4];
                m[o4*4+0] = fmaf(v, w.x, m[o4*4+0]);
                m[o4*4+1] = fmaf(v, w.y, m[o4*4+1]);
                m[o4*4+2] = fmaf(v, w.z, m[o4*4+2]);
                m[o4*4+3] = fmaf(v, w.w, m[o4*4+3]);
            }
        }
        nl = bn2[0];
#pragma unroll
        for (int o = 0; o < 16; o++) nl = fmaf(fmaxf(m[o], 0.0f), W2s[o], nl);
        g_nlog[i] = nl;
        b = (unsigned)batch[i];
    } else {
#pragma unroll
        for (int j = 0; j < 24; j++) h[j] = 0.0f;
    }
    __syncthreads();
    // write h back to st (same pitch) then coalesced store of h2
    if (valid) {
#pragma unroll
        for (int j4 = 0; j4 < 6; j4++)
            st[tid * 7 + j4] = make_float4(h[j4*4], h[j4*4+1], h[j4*4+2], h[j4*4+3]);
    }
    __syncthreads();
    float4* hg = (float4*)g_h2 + (size_t)base * 6;
    for (int idx = threadIdx.x; idx < 1536; idx += 256) {
        int row = idx / 6, c4 = idx % 6;
        if (row < nrows) hg[idx] = st[row * 7 + c4];
    }

    unsigned mask = __match_any_sync(0xffffffffu, b);
    int lane = threadIdx.x & 31;
    if (mask == 0xffffffffu && valid) {
        float mx = nl;
#pragma unroll
        for (int d = 16; d >= 1; d >>= 1) mx = fmaxf(mx, __shfl_xor_sync(0xffffffffu, mx, d));
#pragma unroll
        for (int j = 0; j < 24; j++) {
            float v = bfly24(h[j]);
            if (lane == j) atomicAdd(&g_gsum_h2[b * 24 + j], v);
        }
        if (lane == 24) atomicAdd(&g_cnt[b], 32.0f);
        if (lane == 25) atomicMax(&g_gmax[b], f2ord(mx));
    } else if (valid && b < NG) {
        atomicMax(&g_gmax[b], f2ord(nl));
        atomicAdd(&g_cnt[b], 1.0f);
#pragma unroll
        for (int j = 0; j < 24; j++) atomicAdd(&g_gsum_h2[b * 24 + j], h[j]);
    }
}

// e = exp(nlog - gmax); keep in g_nlog; accumulate per-graph sum (warp-segmented)
__global__ void k_exp(const int* __restrict__ batch, int n) {
    int i = blockIdx.x * blockDim.x + threadIdx.x;
    bool valid = (i < n);
    unsigned b = 0xffffffffu;
    float e = 0.0f;
    if (valid) {
        b = (unsigned)batch[i];
        e = __expf(g_nlog[i] - ord2f(g_gmax[b]));
        g_nlog[i] = e;
    }
    unsigned mask = __match_any_sync(0xffffffffu, b);
    int lane = threadIdx.x & 31;
    if (mask == 0xffffffffu && valid) {
        float s = bfly24(e);
        if (lane == 0) atomicAdd(&g_gsumn[b], s);
    } else if (valid && b < NG) {
        atomicAdd(&g_gsumn[b], e);
    }
}

// n = e/gsum; write out_n; bfeat[b] += n*h2[i]  (staged h2, warp-segmented atomics)
__global__ __launch_bounds__(256) void k_nbf(const int* __restrict__ batch,
                                             float* __restrict__ out_n, int n) {
    __shared__ float4 st[256 * 7];
    int base = blockIdx.x * 256;
    int nrows = n - base; if (nrows > 256) nrows = 256;
    const float4* hg = (const float4*)g_h2 + (size_t)base * 6;
    for (int idx = threadIdx.x; idx < 1536; idx += 256) {
        int row = idx / 6, c4 = idx % 6;
        if (row < nrows) st[row * 7 + c4] = hg[idx];
    }
    __syncthreads();
    int tid = threadIdx.x;
    int i = base + tid;
    bool valid = tid < nrows;
    unsigned b = 0xffffffffu;
    float val = 0.0f;
    float h[24];
    if (valid) {
        b = (unsigned)batch[i];
        val = g_nlog[i] / g_gsumn[b];
        out_n[i] = val;
#pragma unroll
        for (int j4 = 0; j4 < 6; j4++) {
            float4 v = st[tid * 7 + j4];
            h[j4*4+0] = v.x; h[j4*4+1] = v.y; h[j4*4+2] = v.z; h[j4*4+3] = v.w;
        }
    } else {
#pragma unroll
        for (int j = 0; j < 24; j++) h[j] = 0.0f;
    }
    unsigned mask = __match_any_sync(0xffffffffu, b);
    int lane = threadIdx.x & 31;
    if (mask == 0xffffffffu && valid) {
#pragma unroll
        for (int j = 0; j < 24; j++) {
            float v = bfly24(val * h[j]);
            if (lane == j) atomicAdd(&g_bfeat[b * 24 + j], v);
        }
    } else if (valid && b < NG) {
#pragma unroll
        for (int j = 0; j < 24; j++) atomicAdd(&g_bfeat[b * 24 + j], val * h[j]);
    }
}

// per-graph heads
__global__ __launch_bounds__(256) void k_heads(const float* __restrict__ Wg, const float* __restrict__ bg,
                                               const float* __restrict__ Wt, const float* __restrict__ bt,
                                               const float* __restrict__ Wb1, const float* __restrict__ bb1,
                                               const float* __restrict__ Wb2, const float* __restrict__ bb2,
                                               float* __restrict__ out_t, float* __restrict__ out_bb) {
    __shared__ float sBB[NG * 3];
    __shared__ float cmax[3], csum[3];
    int b = threadIdx.x;

    float c = fmaxf(g_cnt[b], 1.0f);
    float g24[24];
#pragma unroll
    for (int j = 0; j < 24; j++) g24[j] = g_gsum_h2[b * 24 + j] / c;
    float t0 = bt[0], t1 = bt[1];
    for (int o = 0; o < 32; o++) {
        float go = bg[o];
#pragma unroll
        for (int k = 0; k < 24; k++) go = fmaf(g24[k], Wg[k * 32 + o], go);
        t0 = fmaf(go, Wt[o * 2 + 0], t0);
        t1 = fmaf(go, Wt[o * 2 + 1], t1);
    }
    float mx = fmaxf(t0, t1);
    float e0 = __expf(t0 - mx), e1 = __expf(t1 - mx);
    float s = e0 + e1;
    out_t[2 * b + 0] = e0 / s;
    out_t[2 * b + 1] = e1 / s;

    float bf[24];
#pragma unroll
    for (int k = 0; k < 24; k++) bf[k] = g_bfeat[b * 24 + k];
    float r16[16];
#pragma unroll
    for (int o = 0; o < 16; o++) {
        float v = bb1[o];
#pragma unroll
        for (int k = 0; k < 24; k++) v = fmaf(bf[k], Wb1[k * 16 + o], v);
        r16[o] = fmaxf(v, 0.0f);
    }
#pragma unroll
    for (int o = 0; o < 3; o++) {
        float v = bb2[o];
#pragma unroll
        for (int k = 0; k < 16; k++) v = fmaf(r16[k], Wb2[k * 3 + o], v);
        sBB[b * 3 + o] = v;
    }
    __syncthreads();
    if (b < 3) {
        float m = -3.4e38f;
        for (int r = 0; r < NG; r++) m = fmaxf(m, sBB[r * 3 + b]);
        float ss = 0.0f;
        for (int r = 0; r < NG; r++) ss += __expf(sBB[r * 3 + b] - m);
        cmax[b] = m; csum[b] = ss;
    }
    __syncthreads();
#pragma unroll
    for (int o = 0; o < 3; o++)
        out_bb[b * 3 + o] = __expf(sBB[b * 3 + o] - cmax[o]) / csum[o];
}

// ---------------- launcher ----------------
extern "C" void kernel_launch(void* const* d_in, const int* in_sizes, int n_in,
                              void* d_out, int out_size) {
    const float* x   = (const float*)d_in[0];
    const int*   ei  = (const int*)d_in[1];
    const int*   bat = (const int*)d_in[2];
    const float *W1 = (const float*)d_in[3],  *b1 = (const float*)d_in[4];
    const float *W2 = (const float*)d_in[5];
    const float *b2 = (const float*)d_in[6];
    const float *Wg = (const float*)d_in[7],  *bg = (const float*)d_in[8];
    const float *Wt = (const float*)d_in[9],  *bt = (const float*)d_in[10];
    const float *Wn1= (const float*)d_in[11], *bn1= (const float*)d_in[12];
    const float *Wn2= (const float*)d_in[13], *bn2= (const float*)d_in[14];
    const float *Wb1= (const float*)d_in[15], *bb1= (const float*)d_in[16];
    const float *Wb2= (const float*)d_in[17], *bb2= (const float*)d_in[18];

    const int N = in_sizes[0] / 32;
    const int E = in_sizes[1] / 2;
    const int* rows = ei;       // edge_index[0] = source
    const int* cols = ei + E;   // edge_index[1] = target

    float* out = (float*)d_out;
    float* out_t  = out;              // [256,2]
    float* out_n  = out + NG * 2;     // [N,1]
    float* out_bb = out + NG * 2 + N; // [256,3]

    const int TB = 256;
    k_init<<<(NG * 24 + TB - 1) / TB, TB>>>();
    k_hist<<<(E / 2 + TB - 1) / TB, TB>>>(cols, E);
    k_blocksum<<<NB, 256>>>();
    k_scanb<<<1, 512>>>(E);
    k_offsets<<<NB, 256>>>();
    k_place<<<(E / 2 + TB - 1) / TB, TB>>>(rows, cols, E);
    k_gemm1<<<(N + 255) / 256, 256>>>(x, W1, N);
    k_aggr1<<<(N + 31) / 32, 256>>>(N);
    k_fin1gemm2<<<(N + 255) / 256, 256>>>(b1, W2, N);
    k_aggr2<<<(N + 31) / 32, 192>>>(N);
    k_fin2<<<(N + 255) / 256, 256>>>(b2, Wn1, bn1, Wn2, bn2, bat, N);
    k_exp<<<(N + TB - 1) / TB, TB>>>(bat, N);
    k_nbf<<<(N + 255) / 256, 256>>>(bat, out_n, N);
    k_heads<<<1, NG>>>(Wg, bg, Wt, bt, Wb1, bb1, Wb2, bb2, out_t, out_bb);
}

// round 5
// speedup vs baseline: 1.9764x; 1.1155x over previous
#include <cuda_runtime.h>
#include <cuda_fp16.h>
#include <math.h>

#define NN 100000
#define NE 3200000
#define NG 256
#define NB 391             // ceil(NN/256)

// -------- scratch --------
__device__ __align__(16) __half g_u1h[NN * 32];   // (x@W1)*dinv, fp16
__device__ __align__(16) __half g_u2h[NN * 24];   // (h1@W2)*dinv, fp16
__device__ __align__(16) __half g_h2h[NN * 24];   // h2, fp16
__device__ __align__(16) float  g_nlog[NN];
__device__ float    g_dinv[NN];
__device__ int      g_cnti[NN];      // self-cleaned in k_offsets
__device__ int      g_off [NN + 1];
__device__ int      g_cur [NN];
__device__ int      g_srt [NE];
__device__ int      g_bsum[NB];
__device__ int      g_boff[NB];
__device__ __align__(16) float g_gsum_h2[NG * 24];
__device__ __align__(16) float g_bfeat  [NG * 24];
__device__ float    g_cnt  [NG];
__device__ unsigned g_gmax [NG];
__device__ float    g_gsumn[NG];

// ---------------- helpers ----------------
__device__ __forceinline__ unsigned f2ord(float f) {
    unsigned u = __float_as_uint(f);
    return (u & 0x80000000u) ? ~u : (u | 0x80000000u);
}
__device__ __forceinline__ float ord2f(unsigned u) {
    return (u & 0x80000000u) ? __uint_as_float(u ^ 0x80000000u) : __uint_as_float(~u);
}
__device__ __forceinline__ float bfly24(float v) {
#pragma unroll
    for (int d = 16; d >= 1; d >>= 1) v += __shfl_xor_sync(0xffffffffu, v, d);
    return v;
}
// accumulate 8 halves (one uint4) into 8 fp32
__device__ __forceinline__ void acc8(float* a, uint4 u) {
    const __half2* hp = (const __half2*)&u;
#pragma unroll
    for (int p = 0; p < 4; p++) {
        float2 f = __half22float2(hp[p]);
        a[p*2+0] += f.x; a[p*2+1] += f.y;
    }
}

// ---------------- kernels ----------------

// in-degree histogram, 2 edges/thread (edge_index is int32)
__global__ void k_hist(const int* __restrict__ cols, int E) {
    int e = (blockIdx.x * blockDim.x + threadIdx.x) * 2;
    if (e + 1 < E) {
        int2 c = *(const int2*)(cols + e);
        if ((unsigned)c.x < NN) atomicAdd(&g_cnti[c.x], 1);
        if ((unsigned)c.y < NN) atomicAdd(&g_cnti[c.y], 1);
    } else if (e < E) {
        unsigned c = (unsigned)cols[e];
        if (c < NN) atomicAdd(&g_cnti[c], 1);
    }
}

// per-256-block sums of histogram + dinv
__global__ __launch_bounds__(256) void k_blocksum() {
    __shared__ int s[256];
    int i = blockIdx.x * 256 + threadIdx.x;
    int v = (i < NN) ? g_cnti[i] : 0;
    if (i < NN) g_dinv[i] = rsqrtf((float)(v + 1));
    s[threadIdx.x] = v;
    __syncthreads();
#pragma unroll
    for (int d = 128; d >= 32; d >>= 1) {
        if (threadIdx.x < d) s[threadIdx.x] += s[threadIdx.x + d];
        __syncthreads();
    }
    if (threadIdx.x < 32) {
        int w = s[threadIdx.x];
#pragma unroll
        for (int d = 16; d >= 1; d >>= 1) w += __shfl_xor_sync(0xffffffffu, w, d);
        if (threadIdx.x == 0) g_bsum[blockIdx.x] = w;
    }
}

// exclusive scan of block sums + zero per-graph scratch
__global__ __launch_bounds__(512) void k_scanb(int E) {
    __shared__ int s[512];
    int t = threadIdx.x;
    // zero per-graph accumulators (6144 + 3*256 floats)
    for (int i = t; i < NG * 24; i += 512) { g_gsum_h2[i] = 0.0f; g_bfeat[i] = 0.0f; }
    if (t < NG) { g_cnt[t] = 0.0f; g_gmax[t] = 0u; g_gsumn[t] = 0.0f; }
    int v = (t < NB) ? g_bsum[t] : 0;
    s[t] = v;
    __syncthreads();
#pragma unroll
    for (int d = 1; d < 512; d <<= 1) {
        int x = (t >= d) ? s[t - d] : 0;
        __syncthreads();
        s[t] += x;
        __syncthreads();
    }
    if (t < NB) g_boff[t] = s[t] - v;
    if (t == 0) g_off[NN] = E;
}

// per-block exclusive scan -> offsets + cursors; self-clean cnti
__global__ __launch_bounds__(256) void k_offsets() {
    __shared__ int s[256];
    int t = threadIdx.x;
    int i = blockIdx.x * 256 + t;
    int v = (i < NN) ? g_cnti[i] : 0;
    s[t] = v;
    __syncthreads();
#pragma unroll
    for (int d = 1; d < 256; d <<= 1) {
        int x = (t >= d) ? s[t - d] : 0;
        __syncthreads();
        s[t] += x;
        __syncthreads();
    }
    if (i < NN) {
        int o = g_boff[blockIdx.x] + s[t] - v;
        g_off[i] = o;
        g_cur[i] = o;
        g_cnti[i] = 0;                        // self-clean for graph replay
    }
}

// place rows into CSR order, 2 edges/thread
__global__ void k_place(const int* __restrict__ rows, const int* __restrict__ cols, int E) {
    int e = (blockIdx.x * blockDim.x + threadIdx.x) * 2;
    if (e + 1 < E) {
        int2 r = *(const int2*)(rows + e);
        int2 c = *(const int2*)(cols + e);
        if ((unsigned)c.x < NN && (unsigned)r.x < NN) g_srt[atomicAdd(&g_cur[c.x], 1)] = r.x;
        if ((unsigned)c.y < NN && (unsigned)r.y < NN) g_srt[atomicAdd(&g_cur[c.y], 1)] = r.y;
    } else if (e < E) {
        unsigned c = (unsigned)cols[e], r = (unsigned)rows[e];
        if (c < NN && r < NN) g_srt[atomicAdd(&g_cur[c], 1)] = (int)r;
    }
}

// u1 = (x @ W1) * dinv  -> fp16  [NN,32]
__global__ __launch_bounds__(256) void k_gemm1(const float* __restrict__ x,
                                               const float* __restrict__ W1, int n) {
    __shared__ float4 Ws[32 * 8];
    __shared__ float4 st[256 * 9];     // pitch 9 float4
    for (int t = threadIdx.x; t < 256; t += 256) Ws[t] = ((const float4*)W1)[t];
    int base = blockIdx.x * 256;
    int nrows = n - base; if (nrows > 256) nrows = 256;
    const float4* xg = (const float4*)x + (size_t)base * 8;
    for (int idx = threadIdx.x; idx < 2048; idx += 256) {
        int row = idx >> 3, c4 = idx & 7;
        if (row < nrows) st[row * 9 + c4] = xg[idx];
    }
    __syncthreads();
    int tid = threadIdx.x;
    if (tid >= nrows) return;
    float a[32];
#pragma unroll
    for (int j = 0; j < 32; j++) a[j] = 0.0f;
#pragma unroll
    for (int k4 = 0; k4 < 8; k4++) {
        float4 xv = st[tid * 9 + k4];
        float xs[4] = {xv.x, xv.y, xv.z, xv.w};
#pragma unroll
        for (int c = 0; c < 4; c++) {
            float v = xs[c];
            int k = k4 * 4 + c;
#pragma unroll
            for (int j4 = 0; j4 < 8; j4++) {
                float4 w = Ws[k * 8 + j4];
                a[j4*4+0] = fmaf(v, w.x, a[j4*4+0]);
                a[j4*4+1] = fmaf(v, w.y, a[j4*4+1]);
                a[j4*4+2] = fmaf(v, w.z, a[j4*4+2]);
                a[j4*4+3] = fmaf(v, w.w, a[j4*4+3]);
            }
        }
    }
    float di = g_dinv[base + tid];
    __half2 hp[16];
#pragma unroll
    for (int p = 0; p < 16; p++) hp[p] = __floats2half2_rn(a[p*2] * di, a[p*2+1] * di);
    uint4* out = (uint4*)g_u1h + (size_t)(base + tid) * 4;
    const uint4* src = (const uint4*)hp;
#pragma unroll
    for (int q = 0; q < 4; q++) out[q] = src[q];
}

// fused: aggregate conv1 (4 thr/node, fp16 gather) + relu/bias + GEMM W2 -> u2 fp16
__global__ __launch_bounds__(128) void k_aggrfin1(const float* __restrict__ b1,
                                                  const float* __restrict__ W2, int n) {
    __shared__ float Ws[32 * 24];
    __shared__ float bs[32];
    __shared__ float hs[32][33];
    for (int t = threadIdx.x; t < 768; t += 128) Ws[t] = W2[t];
    if (threadIdx.x < 32) bs[threadIdx.x] = b1[threadIdx.x];
    int local = threadIdx.x >> 2;
    int sub   = threadIdx.x & 3;       // 8 feats each
    int node  = blockIdx.x * 32 + local;
    bool valid = node < n;
    float acc[8];
#pragma unroll
    for (int f = 0; f < 8; f++) acc[f] = 0.0f;
    float di = 0.0f;
    if (valid) {
        const uint4* U = (const uint4*)g_u1h;
        acc8(acc, U[(size_t)node * 4 + sub]);     // self loop
        int s = g_off[node], e = g_off[node + 1];
        int j = s;
        for (; j + 4 <= e; j += 4) {
            int r0 = g_srt[j], r1 = g_srt[j+1], r2 = g_srt[j+2], r3 = g_srt[j+3];
            uint4 v0 = U[(size_t)r0 * 4 + sub];
            uint4 v1 = U[(size_t)r1 * 4 + sub];
            uint4 v2 = U[(size_t)r2 * 4 + sub];
            uint4 v3 = U[(size_t)r3 * 4 + sub];
            acc8(acc, v0); acc8(acc, v1); acc8(acc, v2); acc8(acc, v3);
        }
        for (; j < e; j++) acc8(acc, U[(size_t)g_srt[j] * 4 + sub]);
        di = g_dinv[node];
#pragma unroll
        for (int f = 0; f < 8; f++)
            hs[local][sub * 8 + f] = fmaxf(di * acc[f] + bs[sub * 8 + f], 0.0f);
    }
    __syncthreads();
    if (!valid) return;
    // each of 4 threads computes 6 of the 24 outputs
    float a[6];
#pragma unroll
    for (int q = 0; q < 6; q++) a[q] = 0.0f;
#pragma unroll
    for (int k = 0; k < 32; k++) {
        float v = hs[local][k];
        const float* wr = &Ws[k * 24 + sub * 6];
#pragma unroll
        for (int q = 0; q < 6; q++) a[q] = fmaf(v, wr[q], a[q]);
    }
    __half2* out = (__half2*)(g_u2h + (size_t)node * 24 + sub * 6);
#pragma unroll
    for (int q = 0; q < 3; q++)
        out[q] = __floats2half2_rn(a[q*2] * di, a[q*2+1] * di);
}

// fused: aggregate conv2 (3 thr/node) + relu/bias -> h2 fp16 + node MLP + per-graph reductions
__global__ __launch_bounds__(192) void k_aggrfin2(const float* __restrict__ b2,
                                                  const float* __restrict__ Wn1, const float* __restrict__ bn1,
                                                  const float* __restrict__ Wn2, const float* __restrict__ bn2,
                                                  const int* __restrict__ batch, int n) {
    __shared__ float W1s[24 * 16];
    __shared__ float b1s[16];
    __shared__ float W2s[16];
    __shared__ float b2s[24];
    __shared__ float hs[64][25];
    for (int t = threadIdx.x; t < 384; t += 192) W1s[t] = Wn1[t];
    if (threadIdx.x < 16) { b1s[threadIdx.x] = bn1[threadIdx.x]; W2s[threadIdx.x] = Wn2[threadIdx.x]; }
    if (threadIdx.x < 24) b2s[threadIdx.x] = b2[threadIdx.x];
    int local = threadIdx.x / 3;
    int sub   = threadIdx.x % 3;       // 8 feats each
    int node  = blockIdx.x * 64 + local;
    bool valid = (node < n) && (local < 64);
    float acc[8];
#pragma unroll
    for (int f = 0; f < 8; f++) acc[f] = 0.0f;
    if (valid) {
        const uint4* U = (const uint4*)g_u2h;
        acc8(acc, U[(size_t)node * 3 + sub]);     // self loop
        int s = g_off[node], e = g_off[node + 1];
        int j = s;
        for (; j + 4 <= e; j += 4) {
            int r0 = g_srt[j], r1 = g_srt[j+1], r2 = g_srt[j+2], r3 = g_srt[j+3];
            uint4 v0 = U[(size_t)r0 * 3 + sub];
            uint4 v1 = U[(size_t)r1 * 3 + sub];
            uint4 v2 = U[(size_t)r2 * 3 + sub];
            uint4 v3 = U[(size_t)r3 * 3 + sub];
            acc8(acc, v0); acc8(acc, v1); acc8(acc, v2); acc8(acc, v3);
        }
        for (; j < e; j++) acc8(acc, U[(size_t)g_srt[j] * 3 + sub]);
        float di = g_dinv[node];
        __half2 hp[4];
#pragma unroll
        for (int p = 0; p < 4; p++) {
            float h0 = fmaxf(di * acc[p*2+0] + b2s[sub*8 + p*2+0], 0.0f);
            float h1 = fmaxf(di * acc[p*2+1] + b2s[sub*8 + p*2+1], 0.0f);
            hs[local][sub*8 + p*2+0] = h0;
            hs[local][sub*8 + p*2+1] = h1;
            hp[p] = __floats2half2_rn(h0, h1);
        }
        ((uint4*)g_h2h)[(size_t)node * 3 + sub] = *(const uint4*)hp;
    }
    __syncthreads();
    // phase 3: warps 0,1 — one node per lane
    if (threadIdx.x >= 64) return;
    int tid = threadIdx.x;
    int node2 = blockIdx.x * 64 + tid;
    bool v2 = node2 < n;
    float h[24];
    float nl = 0.0f;
    unsigned b = 0xffffffffu;
    if (v2) {
#pragma unroll
        for (int k = 0; k < 24; k++) h[k] = hs[tid][k];
        float m[16];
#pragma unroll
        for (int o = 0; o < 16; o++) m[o] = b1s[o];
#pragma unroll
        for (int k = 0; k < 24; k++) {
            float v = h[k];
            const float* wr = &W1s[k * 16];
#pragma unroll
            for (int o = 0; o < 16; o++) m[o] = fmaf(v, wr[o], m[o]);
        }
        nl = bn2[0];
#pragma unroll
        for (int o = 0; o < 16; o++) nl = fmaf(fmaxf(m[o], 0.0f), W2s[o], nl);
        g_nlog[node2] = nl;
        b = (unsigned)batch[node2];
    } else {
#pragma unroll
        for (int k = 0; k < 24; k++) h[k] = 0.0f;
    }
    unsigned mask = __match_any_sync(0xffffffffu, b);
    int lane = tid & 31;
    if (mask == 0xffffffffu && v2) {
        float mx = nl;
#pragma unroll
        for (int d = 16; d >= 1; d >>= 1) mx = fmaxf(mx, __shfl_xor_sync(0xffffffffu, mx, d));
#pragma unroll
        for (int j = 0; j < 24; j++) {
            float v = bfly24(h[j]);
            if (lane == j) atomicAdd(&g_gsum_h2[b * 24 + j], v);
        }
        if (lane == 24) atomicAdd(&g_cnt[b], 32.0f);
        if (lane == 25) atomicMax(&g_gmax[b], f2ord(mx));
    } else if (v2 && b < NG) {
        atomicMax(&g_gmax[b], f2ord(nl));
        atomicAdd(&g_cnt[b], 1.0f);
#pragma unroll
        for (int j = 0; j < 24; j++) atomicAdd(&g_gsum_h2[b * 24 + j], h[j]);
    }
}

// e = exp(nlog - gmax); keep in g_nlog; per-graph sum (warp-segmented)
__global__ void k_exp(const int* __restrict__ batch, int n) {
    int i = blockIdx.x * blockDim.x + threadIdx.x;
    bool valid = (i < n);
    unsigned b = 0xffffffffu;
    float e = 0.0f;
    if (valid) {
        b = (unsigned)batch[i];
        e = __expf(g_nlog[i] - ord2f(g_gmax[b]));
        g_nlog[i] = e;
    }
    unsigned mask = __match_any_sync(0xffffffffu, b);
    int lane = threadIdx.x & 31;
    if (mask == 0xffffffffu && valid) {
        float s = bfly24(e);
        if (lane == 0) atomicAdd(&g_gsumn[b], s);
    } else if (valid && b < NG) {
        atomicAdd(&g_gsumn[b], e);
    }
}

// n = e/gsum; write out_n; bfeat[b] += n*h2[i]  (fp16 staged, warp-segmented)
__global__ __launch_bounds__(256) void k_nbf(const int* __restrict__ batch,
                                             float* __restrict__ out_n, int n) {
    __shared__ uint4 st[256 * 3];
    int base = blockIdx.x * 256;
    int nrows = n - base; if (nrows > 256) nrows = 256;
    const uint4* hg = (const uint4*)g_h2h + (size_t)base * 3;
    for (int idx = threadIdx.x; idx < nrows * 3; idx += 256) st[idx] = hg[idx];
    __syncthreads();
    int tid = threadIdx.x;
    int i = base + tid;
    bool valid = tid < nrows;
    unsigned b = 0xffffffffu;
    float val = 0.0f;
    float h[24];
    if (valid) {
        b = (unsigned)batch[i];
        val = g_nlog[i] / g_gsumn[b];
        out_n[i] = val;
#pragma unroll
        for (int k = 0; k < 3; k++) {
            uint4 u = st[tid * 3 + k];
            const __half2* hp = (const __half2*)&u;
#pragma unroll
            for (int p = 0; p < 4; p++) {
                float2 f = __half22float2(hp[p]);
                h[k*8 + p*2+0] = f.x; h[k*8 + p*2+1] = f.y;
            }
        }
    } else {
#pragma unroll
        for (int j = 0; j < 24; j++) h[j] = 0.0f;
    }
    unsigned mask = __match_any_sync(0xffffffffu, b);
    int lane = threadIdx.x & 31;
    if (mask == 0xffffffffu && valid) {
#pragma unroll
        for (int j = 0; j < 24; j++) {
            float v = bfly24(val * h[j]);
            if (lane == j) atomicAdd(&g_bfeat[b * 24 + j], v);
        }
    } else if (valid && b < NG) {
#pragma unroll
        for (int j = 0; j < 24; j++) atomicAdd(&g_bfeat[b * 24 + j], val * h[j]);
    }
}

// per-graph heads
__global__ __launch_bounds__(256) void k_heads(const float* __restrict__ Wg, const float* __restrict__ bg,
                                               const float* __restrict__ Wt, const float* __restrict__ bt,
                                               const float* __restrict__ Wb1, const float* __restrict__ bb1,
                                               const float* __restrict__ Wb2, const float* __restrict__ bb2,
                                               float* __restrict__ out_t, float* __restrict__ out_bb) {
    __shared__ float sBB[NG * 3];
    __shared__ float cmax[3], csum[3];
    int b = threadIdx.x;

    float c = fmaxf(g_cnt[b], 1.0f);
    float g24[24];
#pragma unroll
    for (int j = 0; j < 24; j++) g24[j] = g_gsum_h2[b * 24 + j] / c;
    float t0 = bt[0], t1 = bt[1];
    for (int o = 0; o < 32; o++) {
        float go = bg[o];
#pragma unroll
        for (int k = 0; k < 24; k++) go = fmaf(g24[k], Wg[k * 32 + o], go);
        t0 = fmaf(go, Wt[o * 2 + 0], t0);
        t1 = fmaf(go, Wt[o * 2 + 1], t1);
    }
    float mx = fmaxf(t0, t1);
    float e0 = __expf(t0 - mx), e1 = __expf(t1 - mx);
    float s = e0 + e1;
    out_t[2 * b + 0] = e0 / s;
    out_t[2 * b + 1] = e1 / s;

    float bf[24];
#pragma unroll
    for (int k = 0; k < 24; k++) bf[k] = g_bfeat[b * 24 + k];
    float r16[16];
#pragma unroll
    for (int o = 0; o < 16; o++) {
        float v = bb1[o];
#pragma unroll
        for (int k = 0; k < 24; k++) v = fmaf(bf[k], Wb1[k * 16 + o], v);
        r16[o] = fmaxf(v, 0.0f);
    }
#pragma unroll
    for (int o = 0; o < 3; o++) {
        float v = bb2[o];
#pragma unroll
        for (int k = 0; k < 16; k++) v = fmaf(r16[k], Wb2[k * 3 + o], v);
        sBB[b * 3 + o] = v;
    }
    __syncthreads();
    if (b < 3) {
        float m = -3.4e38f;
        for (int r = 0; r < NG; r++) m = fmaxf(m, sBB[r * 3 + b]);
        float ss = 0.0f;
        for (int r = 0; r < NG; r++) ss += __expf(sBB[r * 3 + b] - m);
        cmax[b] = m; csum[b] = ss;
    }
    __syncthreads();
#pragma unroll
    for (int o = 0; o < 3; o++)
        out_bb[b * 3 + o] = __expf(sBB[b * 3 + o] - cmax[o]) / csum[o];
}

// ---------------- launcher ----------------
extern "C" void kernel_launch(void* const* d_in, const int* in_sizes, int n_in,
                              void* d_out, int out_size) {
    const float* x   = (const float*)d_in[0];
    const int*   ei  = (const int*)d_in[1];
    const int*   bat = (const int*)d_in[2];
    const float *W1 = (const float*)d_in[3],  *b1 = (const float*)d_in[4];
    const float *W2 = (const float*)d_in[5];
    const float *b2 = (const float*)d_in[6];
    const float *Wg = (const float*)d_in[7],  *bg = (const float*)d_in[8];
    const float *Wt = (const float*)d_in[9],  *bt = (const float*)d_in[10];
    const float *Wn1= (const float*)d_in[11], *bn1= (const float*)d_in[12];
    const float *Wn2= (const float*)d_in[13], *bn2= (const float*)d_in[14];
    const float *Wb1= (const float*)d_in[15], *bb1= (const float*)d_in[16];
    const float *Wb2= (const float*)d_in[17], *bb2= (const float*)d_in[18];

    const int N = in_sizes[0] / 32;
    const int E = in_sizes[1] / 2;
    const int* rows = ei;       // edge_index[0] = source
    const int* cols = ei + E;   // edge_index[1] = target

    float* out = (float*)d_out;
    float* out_t  = out;              // [256,2]
    float* out_n  = out + NG * 2;     // [N,1]
    float* out_bb = out + NG * 2 + N; // [256,3]

    const int TB = 256;
    k_hist<<<(E / 2 + TB - 1) / TB, TB>>>(cols, E);
    k_blocksum<<<NB, 256>>>();
    k_scanb<<<1, 512>>>(E);
    k_offsets<<<NB, 256>>>();
    k_place<<<(E / 2 + TB - 1) / TB, TB>>>(rows, cols, E);
    k_gemm1<<<(N + 255) / 256, 256>>>(x, W1, N);
    k_aggrfin1<<<(N + 31) / 32, 128>>>(b1, W2, N);
    k_aggrfin2<<<(N + 63) / 64, 192>>>(b2, Wn1, bn1, Wn2, bn2, bat, N);
    k_exp<<<(N + TB - 1) / TB, TB>>>(bat, N);
    k_nbf<<<(N + 255) / 256, 256>>>(bat, out_n, N);
    k_heads<<<1, NG>>>(Wg, bg, Wt, bt, Wb1, bb1, Wb2, bb2, out_t, out_bb);
}